// round 5
// baseline (speedup 1.0000x reference)
#include <cuda_runtime.h>

// Problem constants: B=4, N=2048, D=768, OUT=768
#define BM 128
#define BN 128
#define BK 16
#define TM 8
#define TN 8

// Scratch (no device allocation allowed -> __device__ globals)
__device__ float g_qkv[3u * 8192u * 768u];      // Q,K,V each [8192, 768]
__device__ float g_scores[4u * 2048u * 2048u];  // per-batch attention scores

// ---------------------------------------------------------------------------
// Batched tiled SGEMM: C = alpha * A @ op(B)
//   A: [M, K] row-major (lda), B: [K, N] row-major (ldb) or, if TRANSB,
//   B stored [N, K] row-major and we compute A @ B^T.
//   blockIdx.z selects the batch via the given strides.
// 128x128 tile, BK=16, 256 threads, 8x8 per-thread microtile.
// All dims in this problem are multiples of the tile sizes -> no bounds checks.
// ---------------------------------------------------------------------------
template<bool TRANSB>
__global__ __launch_bounds__(256, 2)
void sgemm_kernel(const float* __restrict__ A, const float* __restrict__ Bm,
                  float* __restrict__ C,
                  int lda, int ldb, int ldc, int K,
                  long sA, long sB, long sC, float alpha)
{
    __shared__ __align__(16) float As[BK][BM];
    __shared__ __align__(16) float Bs[BK][BN];

    const float* Ab = A  + (long)blockIdx.z * sA;
    const float* Bb = Bm + (long)blockIdx.z * sB;
    float*       Cb = C  + (long)blockIdx.z * sC;

    const int m0 = blockIdx.y * BM;
    const int n0 = blockIdx.x * BN;
    const int tid = threadIdx.x;
    const int ty = tid >> 4;   // 0..15
    const int tx = tid & 15;   // 0..15

    float acc[TM][TN];
    #pragma unroll
    for (int i = 0; i < TM; i++)
        #pragma unroll
        for (int j = 0; j < TN; j++) acc[i][j] = 0.0f;

    for (int k0 = 0; k0 < K; k0 += BK) {
        // --- load A tile: 128 rows x 16 cols, transposed into As[k][m] ---
        #pragma unroll
        for (int s = tid; s < (BM * BK) / 4; s += 256) {
            int row = s >> 2, cv = s & 3;
            float4 v = *(const float4*)(Ab + (long)(m0 + row) * lda + k0 + cv * 4);
            As[cv * 4 + 0][row] = v.x;
            As[cv * 4 + 1][row] = v.y;
            As[cv * 4 + 2][row] = v.z;
            As[cv * 4 + 3][row] = v.w;
        }
        // --- load B tile into Bs[k][n] ---
        if (TRANSB) {
            #pragma unroll
            for (int s = tid; s < (BN * BK) / 4; s += 256) {
                int n = s >> 2, cv = s & 3;
                float4 v = *(const float4*)(Bb + (long)(n0 + n) * ldb + k0 + cv * 4);
                Bs[cv * 4 + 0][n] = v.x;
                Bs[cv * 4 + 1][n] = v.y;
                Bs[cv * 4 + 2][n] = v.z;
                Bs[cv * 4 + 3][n] = v.w;
            }
        } else {
            #pragma unroll
            for (int s = tid; s < (BN * BK) / 4; s += 256) {
                int kr = s >> 5, nv = s & 31;
                *(float4*)&Bs[kr][nv * 4] =
                    *(const float4*)(Bb + (long)(k0 + kr) * ldb + n0 + nv * 4);
            }
        }
        __syncthreads();

        // --- compute ---
        #pragma unroll
        for (int k = 0; k < BK; k++) {
            float4 a0 = *(const float4*)&As[k][ty * TM];
            float4 a1 = *(const float4*)&As[k][ty * TM + 4];
            float4 b0 = *(const float4*)&Bs[k][tx * TN];
            float4 b1 = *(const float4*)&Bs[k][tx * TN + 4];
            float a[8] = {a0.x, a0.y, a0.z, a0.w, a1.x, a1.y, a1.z, a1.w};
            float b[8] = {b0.x, b0.y, b0.z, b0.w, b1.x, b1.y, b1.z, b1.w};
            #pragma unroll
            for (int i = 0; i < 8; i++)
                #pragma unroll
                for (int j = 0; j < 8; j++)
                    acc[i][j] = fmaf(a[i], b[j], acc[i][j]);
        }
        __syncthreads();
    }

    // --- epilogue ---
    #pragma unroll
    for (int i = 0; i < TM; i++) {
        float* cp = Cb + (long)(m0 + ty * TM + i) * ldc + n0 + tx * TN;
        float4 v0 = make_float4(acc[i][0] * alpha, acc[i][1] * alpha,
                                acc[i][2] * alpha, acc[i][3] * alpha);
        float4 v1 = make_float4(acc[i][4] * alpha, acc[i][5] * alpha,
                                acc[i][6] * alpha, acc[i][7] * alpha);
        *(float4*)cp       = v0;
        *(float4*)(cp + 4) = v1;
    }
}

// ---------------------------------------------------------------------------
// Row softmax for 2048-wide rows. One block (256 threads) per row; each
// thread holds 8 elements (2 float4). Numerically stable (subtract row max).
// ---------------------------------------------------------------------------
__global__ __launch_bounds__(256)
void softmax2048(float* __restrict__ S)
{
    float* p = S + (long)blockIdx.x * 2048;
    const int tid = threadIdx.x;

    float4 a = ((const float4*)p)[tid];
    float4 b = ((const float4*)p)[tid + 256];

    __shared__ float sred[8];

    // ---- row max ----
    float mx = fmaxf(fmaxf(fmaxf(a.x, a.y), fmaxf(a.z, a.w)),
                     fmaxf(fmaxf(b.x, b.y), fmaxf(b.z, b.w)));
    #pragma unroll
    for (int o = 16; o; o >>= 1) mx = fmaxf(mx, __shfl_xor_sync(0xffffffffu, mx, o));
    if ((tid & 31) == 0) sred[tid >> 5] = mx;
    __syncthreads();
    if (tid < 32) {
        float m = (tid < 8) ? sred[tid] : -3.4e38f;
        #pragma unroll
        for (int o = 4; o; o >>= 1) m = fmaxf(m, __shfl_xor_sync(0xffffffffu, m, o));
        if (tid == 0) sred[0] = m;
    }
    __syncthreads();
    mx = sred[0];
    __syncthreads();

    // ---- exp + row sum ----
    a.x = __expf(a.x - mx); a.y = __expf(a.y - mx);
    a.z = __expf(a.z - mx); a.w = __expf(a.w - mx);
    b.x = __expf(b.x - mx); b.y = __expf(b.y - mx);
    b.z = __expf(b.z - mx); b.w = __expf(b.w - mx);

    float s = a.x + a.y + a.z + a.w + b.x + b.y + b.z + b.w;
    #pragma unroll
    for (int o = 16; o; o >>= 1) s += __shfl_xor_sync(0xffffffffu, s, o);
    if ((tid & 31) == 0) sred[tid >> 5] = s;
    __syncthreads();
    if (tid < 32) {
        float t = (tid < 8) ? sred[tid] : 0.0f;
        #pragma unroll
        for (int o = 4; o; o >>= 1) t += __shfl_xor_sync(0xffffffffu, t, o);
        if (tid == 0) sred[0] = t;
    }
    __syncthreads();
    const float inv = 1.0f / sred[0];

    a.x *= inv; a.y *= inv; a.z *= inv; a.w *= inv;
    b.x *= inv; b.y *= inv; b.z *= inv; b.w *= inv;
    ((float4*)p)[tid]       = a;
    ((float4*)p)[tid + 256] = b;
}

// ---------------------------------------------------------------------------
// Launch: 4 kernels, all graph-capturable, no allocations.
// ---------------------------------------------------------------------------
extern "C" void kernel_launch(void* const* d_in, const int* in_sizes, int n_in,
                              void* d_out, int out_size)
{
    const float* x = (const float*)d_in[0];   // [4, 2048, 768]
    const float* w = (const float*)d_in[1];   // [3, 768, 768]
    float* out = (float*)d_out;               // [4, 2048, 768]

    float *qkv, *scores;
    cudaGetSymbolAddress((void**)&qkv, g_qkv);
    cudaGetSymbolAddress((void**)&scores, g_scores);

    const long MO = 8192L * 768;   // one of Q/K/V (full)
    const long NB = 2048L * 768;   // per-batch Q/K/V slab
    const long SB = 2048L * 2048;  // per-batch scores

    // 1) QKV projection: [8192,768] @ [768,768] per weight (z = 0..2)
    sgemm_kernel<false><<<dim3(6, 64, 3), 256>>>(
        x, w, qkv,
        /*lda*/768, /*ldb*/768, /*ldc*/768, /*K*/768,
        /*sA*/0L, /*sB*/768L * 768, /*sC*/MO, 1.0f);

    // 2) scores = Q @ K^T / 8 per batch (z = 0..3)
    sgemm_kernel<true><<<dim3(16, 16, 4), 256>>>(
        qkv, qkv + MO, scores,
        /*lda*/768, /*ldb*/768, /*ldc*/2048, /*K*/768,
        /*sA*/NB, /*sB*/NB, /*sC*/SB, 0.125f);

    // 3) softmax over the last axis (8192 rows of 2048)
    softmax2048<<<8192, 256>>>(scores);

    // 4) out = P @ V per batch (z = 0..3)
    sgemm_kernel<false><<<dim3(6, 16, 4), 256>>>(
        scores, qkv + 2 * MO, out,
        /*lda*/2048, /*ldb*/768, /*ldc*/768, /*K*/2048,
        /*sA*/SB, /*sB*/NB, /*sC*/NB, 1.0f);
}

// round 12
// speedup vs baseline: 2.7933x; 2.7933x over previous
#include <cuda_runtime.h>
#include <cuda_bf16.h>
#include <cstdint>

// Problem: B=4, N=2048, D=OUT=768.  Threshold rel_err < 1e-3.
// tcgen05/TMA unavailable (ptxas targets base sm_103) -> use arch-portable
// tensor path: mma.sync m16n8k16 bf16 + ldmatrix + cp.async.
// Split-precision bf16x3: X = Xh + Xl, D = Ah*Bh + Ah*Bl + Al*Bh (fp32 accum).

#define BM 128
#define BN 128
#define BK 64                 // 64 bf16 = 128 B rows
#define HALF_B 16384          // one operand half tile: 128 rows * 128 B
#define STAGE_B (4 * HALF_B)  // Ah, Al, Bh, Bl
#define DYN_SMEM (2 * STAGE_B)

// ---------------- scratch (device globals; no allocations allowed) ----------
__device__ __nv_bfloat16 g_xh[8192u * 768u],        g_xl[8192u * 768u];
__device__ __nv_bfloat16 g_wth[3u * 768u * 768u],   g_wtl[3u * 768u * 768u];
__device__ __nv_bfloat16 g_qkh[2u * 8192u * 768u],  g_qkl[2u * 8192u * 768u]; // Q,K
__device__ __nv_bfloat16 g_vth[768u * 8192u],       g_vtl[768u * 8192u];      // V^T
__device__ float         g_scores[4u * 2048u * 2048u];
__device__ __nv_bfloat16 g_ph[4u * 2048u * 2048u],  g_pl[4u * 2048u * 2048u];

// ---------------- helpers ----------------------------------------------------
__device__ __forceinline__ uint32_t smem_u32(const void* p) {
    uint32_t a;
    asm("{ .reg .u64 t; cvta.to.shared.u64 t, %1; cvt.u32.u64 %0, t; }" : "=r"(a) : "l"(p));
    return a;
}
__device__ __forceinline__ void cp16(uint32_t s, const void* g) {
    asm volatile("cp.async.cg.shared.global [%0], [%1], 16;" :: "r"(s), "l"(g));
}
#define CP_COMMIT() asm volatile("cp.async.commit_group;" ::: "memory")
#define CP_WAIT(n)  asm volatile("cp.async.wait_group %0;" :: "n"(n) : "memory")

__device__ __forceinline__ void ldsm4(uint32_t* r, uint32_t a) {
    asm volatile("ldmatrix.sync.aligned.m8n8.x4.shared.b16 {%0,%1,%2,%3}, [%4];"
                 : "=r"(r[0]), "=r"(r[1]), "=r"(r[2]), "=r"(r[3]) : "r"(a));
}
__device__ __forceinline__ void mma16816(float* c, const uint32_t* a, const uint32_t* b) {
    asm volatile(
        "mma.sync.aligned.m16n8k16.row.col.f32.bf16.bf16.f32 "
        "{%0,%1,%2,%3}, {%4,%5,%6,%7}, {%8,%9}, {%0,%1,%2,%3};"
        : "+f"(c[0]), "+f"(c[1]), "+f"(c[2]), "+f"(c[3])
        : "r"(a[0]), "r"(a[1]), "r"(a[2]), "r"(a[3]), "r"(b[0]), "r"(b[1]));
}
__device__ __forceinline__ void split2(float v, __nv_bfloat16& h, __nv_bfloat16& l) {
    h = __float2bfloat16(v);
    l = __float2bfloat16(v - __bfloat162float(h));
}

// ---------------------------------------------------------------------------
// Split-bf16 GEMM: D[M,N] = split(A)[M,K] @ split(B)[N,K]^T (both K-major).
// OUTMODE 0: split bf16 row-major [m,n]; 1: split bf16 transposed [n,m];
// OUTMODE 2: fp32 * scale row-major.
// 256 threads, 8 warps (2x4), warp tile 64x32, double-buffered cp.async.
// ---------------------------------------------------------------------------
template<int OUTMODE>
__global__ __launch_bounds__(256, 1)
void gemm_mma(const __nv_bfloat16* __restrict__ Ah_, const __nv_bfloat16* __restrict__ Al_,
              const __nv_bfloat16* __restrict__ Bh_, const __nv_bfloat16* __restrict__ Bl_,
              void* __restrict__ outh, void* __restrict__ outl,
              int lda, int ldb, int K, long sA, long sB, long sOut,
              int ldc, float scale)
{
    extern __shared__ char smarr[];
    const uint32_t smb = smem_u32(smarr);
    const int tid = threadIdx.x, lane = tid & 31, wid = tid >> 5;
    const long bz = blockIdx.z;

    const __nv_bfloat16* A0 = Ah_ + bz * sA;
    const __nv_bfloat16* A1 = Al_ + bz * sA;
    const __nv_bfloat16* B0 = Bh_ + bz * sB;
    const __nv_bfloat16* B1 = Bl_ + bz * sB;

    const int m0 = blockIdx.y * BM;
    const int n0 = blockIdx.x * BN;
    const int wm = wid >> 2;          // 0..1  -> 64-row band
    const int wn = wid & 3;           // 0..3  -> 32-col band

    float acc[4][4][4];
    #pragma unroll
    for (int i = 0; i < 4; ++i)
        #pragma unroll
        for (int j = 0; j < 4; ++j)
            #pragma unroll
            for (int f = 0; f < 4; ++f) acc[i][j][f] = 0.0f;

    // cp.async layout: idx = tid + i*256 -> row = idx>>3 (0..127), chunk = idx&7
    const int ldRow = tid >> 3;
    const int ldCh  = tid & 7;

    auto load_stage = [&](int s, int k0) {
        const uint32_t sb = smb + s * STAGE_B;
        #pragma unroll
        for (int i = 0; i < 4; ++i) {
            const int row = ldRow + i * 32;
            const uint32_t dst = sb + row * 128 + (((ldCh) ^ (row & 7)) << 4);
            const long ka = (long)(m0 + row) * lda + k0 + ldCh * 8;
            const long kb = (long)(n0 + row) * ldb + k0 + ldCh * 8;
            cp16(dst,              A0 + ka);
            cp16(dst +     HALF_B, A1 + ka);
            cp16(dst + 2 * HALF_B, B0 + kb);
            cp16(dst + 3 * HALF_B, B1 + kb);
        }
    };

    // ldmatrix per-lane geometry (row & 7 == lane & 7 always)
    const int aRow = (lane & 7) + (lane & 8);          // 0..15 within m16
    const int aChA = (lane >> 4) & 1;                  // k-chunk select for A
    const int bRow = (lane & 7) + ((lane & 16) >> 1);  // 0..15 within n16
    const int bChA = (lane >> 3) & 1;                  // k-chunk select for B
    const int lxor = lane & 7;

    const int T = K / BK;
    load_stage(0, 0);
    CP_COMMIT();

    for (int t = 0; t < T; ++t) {
        if (t + 1 < T) { load_stage((t + 1) & 1, (t + 1) * BK); CP_COMMIT(); CP_WAIT(1); }
        else           { CP_WAIT(0); }
        __syncthreads();

        const uint32_t sb = smb + (t & 1) * STAGE_B;
        #pragma unroll
        for (int ks = 0; ks < 4; ++ks) {
            uint32_t bh[2][4], bl[2][4];
            #pragma unroll
            for (int ng = 0; ng < 2; ++ng) {
                const int row = wn * 32 + ng * 16 + bRow;
                const uint32_t rb = sb + 2 * HALF_B + row * 128
                                  + (((ks * 2 + bChA) ^ lxor) << 4);
                ldsm4(bh[ng], rb);
                ldsm4(bl[ng], rb + HALF_B);
            }
            #pragma unroll
            for (int mi = 0; mi < 4; ++mi) {
                uint32_t ah[4], al[4];
                const int row = wm * 64 + mi * 16 + aRow;
                const uint32_t ra = sb + row * 128
                                  + (((ks * 2 + aChA) ^ lxor) << 4);
                ldsm4(ah, ra);
                ldsm4(al, ra + HALF_B);
                #pragma unroll
                for (int ni = 0; ni < 4; ++ni) {
                    const int ng = ni >> 1, off = (ni & 1) * 2;
                    mma16816(acc[mi][ni], ah, &bh[ng][off]);
                    mma16816(acc[mi][ni], ah, &bl[ng][off]);
                    mma16816(acc[mi][ni], al, &bh[ng][off]);
                }
            }
        }
        __syncthreads();
    }

    // ---- epilogue ----
    const int rl = lane >> 2;          // 0..7
    const int cl = (lane & 3) * 2;     // 0,2,4,6

    #pragma unroll
    for (int mi = 0; mi < 4; ++mi) {
        #pragma unroll
        for (int ni = 0; ni < 4; ++ni) {
            const int row = m0 + wm * 64 + mi * 16 + rl;
            const int col = n0 + wn * 32 + ni * 8 + cl;
            const float* c = acc[mi][ni];

            if (OUTMODE == 0) {
                __nv_bfloat16* oh = (__nv_bfloat16*)outh + bz * sOut;
                __nv_bfloat16* ol = (__nv_bfloat16*)outl + bz * sOut;
                #pragma unroll
                for (int hrow = 0; hrow < 2; ++hrow) {
                    const long base = (long)(row + hrow * 8) * ldc + col;
                    __nv_bfloat162 hv, lv;
                    split2(c[hrow * 2 + 0], hv.x, lv.x);
                    split2(c[hrow * 2 + 1], hv.y, lv.y);
                    *(__nv_bfloat162*)(oh + base) = hv;
                    *(__nv_bfloat162*)(ol + base) = lv;
                }
            } else if (OUTMODE == 1) {
                __nv_bfloat16* oh = (__nv_bfloat16*)outh;
                __nv_bfloat16* ol = (__nv_bfloat16*)outl;
                #pragma unroll
                for (int hrow = 0; hrow < 2; ++hrow) {
                    #pragma unroll
                    for (int e = 0; e < 2; ++e) {
                        const long o = (long)(col + e) * ldc + row + hrow * 8;
                        __nv_bfloat16 h, l;
                        split2(c[hrow * 2 + e], h, l);
                        oh[o] = h;
                        ol[o] = l;
                    }
                }
            } else {
                float* o = (float*)outh + bz * sOut;
                #pragma unroll
                for (int hrow = 0; hrow < 2; ++hrow) {
                    const long base = (long)(row + hrow * 8) * ldc + col;
                    float2 v = make_float2(c[hrow * 2 + 0] * scale,
                                           c[hrow * 2 + 1] * scale);
                    *(float2*)(o + base) = v;
                }
            }
        }
    }
}

// ---------------------------------------------------------------------------
// fp32 -> (hi, lo) bf16 split. One thread = 8 contiguous elements.
// ---------------------------------------------------------------------------
__global__ __launch_bounds__(256)
void split_f32(const float* __restrict__ X, __nv_bfloat16* __restrict__ H,
               __nv_bfloat16* __restrict__ L)
{
    const long i = ((long)blockIdx.x * 256 + threadIdx.x) * 8;
    float4 a = *(const float4*)(X + i);
    float4 b = *(const float4*)(X + i + 4);
    float v[8] = {a.x, a.y, a.z, a.w, b.x, b.y, b.z, b.w};
    #pragma unroll
    for (int j = 0; j < 4; ++j) {
        __nv_bfloat162 hv, lv;
        split2(v[2 * j],     hv.x, lv.x);
        split2(v[2 * j + 1], hv.y, lv.y);
        *(__nv_bfloat162*)(H + i + 2 * j) = hv;
        *(__nv_bfloat162*)(L + i + 2 * j) = lv;
    }
}

// ---------------------------------------------------------------------------
// W[3,768,768] (K x N) -> W^T[3,768,768] (N x K), split bf16.
// ---------------------------------------------------------------------------
__global__ __launch_bounds__(256)
void transpose_w(const float* __restrict__ W, __nv_bfloat16* __restrict__ Th,
                 __nv_bfloat16* __restrict__ Tl)
{
    __shared__ float t[32][33];
    const int z = blockIdx.z;
    const int k0 = blockIdx.y * 32, n0 = blockIdx.x * 32;
    const float* Wz = W + (long)z * 768 * 768;
    #pragma unroll
    for (int i = 0; i < 4; ++i)
        t[threadIdx.y + 8 * i][threadIdx.x] =
            Wz[(long)(k0 + threadIdx.y + 8 * i) * 768 + n0 + threadIdx.x];
    __syncthreads();
    #pragma unroll
    for (int i = 0; i < 4; ++i) {
        float v = t[threadIdx.x][threadIdx.y + 8 * i];
        long o = (long)z * 768 * 768 + (long)(n0 + threadIdx.y + 8 * i) * 768
                 + k0 + threadIdx.x;
        __nv_bfloat16 h, l;
        split2(v, h, l);
        Th[o] = h;
        Tl[o] = l;
    }
}

// ---------------------------------------------------------------------------
// Row softmax over 2048-wide fp32 rows; writes split-bf16 P.
// ---------------------------------------------------------------------------
__global__ __launch_bounds__(256)
void softmax2048(const float* __restrict__ S, __nv_bfloat16* __restrict__ Ph,
                 __nv_bfloat16* __restrict__ Pl)
{
    const float* p = S + (long)blockIdx.x * 2048;
    const int tid = threadIdx.x;

    float4 a = ((const float4*)p)[2 * tid];
    float4 b = ((const float4*)p)[2 * tid + 1];

    __shared__ float sred[8];

    float mx = fmaxf(fmaxf(fmaxf(a.x, a.y), fmaxf(a.z, a.w)),
                     fmaxf(fmaxf(b.x, b.y), fmaxf(b.z, b.w)));
    #pragma unroll
    for (int o = 16; o; o >>= 1) mx = fmaxf(mx, __shfl_xor_sync(0xffffffffu, mx, o));
    if ((tid & 31) == 0) sred[tid >> 5] = mx;
    __syncthreads();
    if (tid < 32) {
        float m = (tid < 8) ? sred[tid] : -3.4e38f;
        #pragma unroll
        for (int o = 4; o; o >>= 1) m = fmaxf(m, __shfl_xor_sync(0xffffffffu, m, o));
        if (tid == 0) sred[0] = m;
    }
    __syncthreads();
    mx = sred[0];
    __syncthreads();

    a.x = __expf(a.x - mx); a.y = __expf(a.y - mx);
    a.z = __expf(a.z - mx); a.w = __expf(a.w - mx);
    b.x = __expf(b.x - mx); b.y = __expf(b.y - mx);
    b.z = __expf(b.z - mx); b.w = __expf(b.w - mx);

    float s = a.x + a.y + a.z + a.w + b.x + b.y + b.z + b.w;
    #pragma unroll
    for (int o = 16; o; o >>= 1) s += __shfl_xor_sync(0xffffffffu, s, o);
    if ((tid & 31) == 0) sred[tid >> 5] = s;
    __syncthreads();
    if (tid < 32) {
        float t2 = (tid < 8) ? sred[tid] : 0.0f;
        #pragma unroll
        for (int o = 4; o; o >>= 1) t2 += __shfl_xor_sync(0xffffffffu, t2, o);
        if (tid == 0) sred[0] = t2;
    }
    __syncthreads();
    const float inv = 1.0f / sred[0];

    float v[8] = {a.x * inv, a.y * inv, a.z * inv, a.w * inv,
                  b.x * inv, b.y * inv, b.z * inv, b.w * inv};
    const long base = (long)blockIdx.x * 2048 + tid * 8;
    #pragma unroll
    for (int j = 0; j < 4; ++j) {
        __nv_bfloat162 hv, lv;
        split2(v[2 * j],     hv.x, lv.x);
        split2(v[2 * j + 1], hv.y, lv.y);
        *(__nv_bfloat162*)(Ph + base + 2 * j) = hv;
        *(__nv_bfloat162*)(Pl + base + 2 * j) = lv;
    }
}

// ---------------------------------------------------------------------------
extern "C" void kernel_launch(void* const* d_in, const int* in_sizes, int n_in,
                              void* d_out, int out_size)
{
    const float* x = (const float*)d_in[0];   // [4, 2048, 768]
    const float* w = (const float*)d_in[1];   // [3, 768, 768]
    float* out = (float*)d_out;               // [4, 2048, 768]

    __nv_bfloat16 *xh, *xl, *wth, *wtl, *qkh, *qkl, *vth, *vtl, *ph, *pl;
    float* scores;
    cudaGetSymbolAddress((void**)&xh, g_xh);   cudaGetSymbolAddress((void**)&xl, g_xl);
    cudaGetSymbolAddress((void**)&wth, g_wth); cudaGetSymbolAddress((void**)&wtl, g_wtl);
    cudaGetSymbolAddress((void**)&qkh, g_qkh); cudaGetSymbolAddress((void**)&qkl, g_qkl);
    cudaGetSymbolAddress((void**)&vth, g_vth); cudaGetSymbolAddress((void**)&vtl, g_vtl);
    cudaGetSymbolAddress((void**)&ph, g_ph);   cudaGetSymbolAddress((void**)&pl, g_pl);
    cudaGetSymbolAddress((void**)&scores, g_scores);

    cudaFuncSetAttribute(gemm_mma<0>, cudaFuncAttributeMaxDynamicSharedMemorySize, DYN_SMEM);
    cudaFuncSetAttribute(gemm_mma<1>, cudaFuncAttributeMaxDynamicSharedMemorySize, DYN_SMEM);
    cudaFuncSetAttribute(gemm_mma<2>, cudaFuncAttributeMaxDynamicSharedMemorySize, DYN_SMEM);

    const long MO = 8192L * 768;      // one Q/K slab
    const long NB = 2048L * 768;      // per-batch token slab
    const long SB = 2048L * 2048;     // per-batch scores

    // 0) split inputs
    split_f32<<<3072, 256>>>(x, xh, xl);
    transpose_w<<<dim3(24, 24, 3), dim3(32, 8)>>>(w, wth, wtl);

    // 1a) Q, K = x @ W{0,1}  -> split bf16, K-major [token, dim]
    gemm_mma<0><<<dim3(6, 64, 2), 256, DYN_SMEM>>>(
        xh, xl, wth, wtl, qkh, qkl,
        768, 768, 768, /*sA*/0L, /*sB*/768L * 768, /*sOut*/MO, /*ldc*/768, 1.0f);

    // 1b) V = x @ W2 -> split bf16 TRANSPOSED [dim, token(8192)]
    gemm_mma<1><<<dim3(6, 64, 1), 256, DYN_SMEM>>>(
        xh, xl, wth + 2L * 768 * 768, wtl + 2L * 768 * 768, vth, vtl,
        768, 768, 768, 0L, 0L, 0L, /*ldc(trans)*/8192, 1.0f);

    // 2) scores = Q @ K^T / 8  (fp32)
    gemm_mma<2><<<dim3(16, 16, 4), 256, DYN_SMEM>>>(
        qkh, qkl, qkh + MO, qkl + MO, scores, nullptr,
        768, 768, 768, /*sA*/NB, /*sB*/NB, /*sOut*/SB, /*ldc*/2048, 0.125f);

    // 3) softmax rows -> split bf16 P
    softmax2048<<<8192, 256>>>(scores, ph, pl);

    // 4) out = P @ V  (B = V^T, K-major over tokens; per-batch offset 2048 cols)
    gemm_mma<2><<<dim3(6, 16, 4), 256, DYN_SMEM>>>(
        ph, pl, vth, vtl, out, nullptr,
        2048, 8192, 2048, /*sA*/SB, /*sB*/2048L, /*sOut*/NB, /*ldc*/768, 1.0f);
}